// round 1
// baseline (speedup 1.0000x reference)
#include <cuda_runtime.h>
#include <math.h>

#define THREADS   128
#define WARPS     (THREADS/32)
#define F_IN      83
#define F_PAD     84          // pad so rows are 16B-multiple and LDS.128-friendly
#define DD        32

// Shared layout (floats):
//   sIn : WARPS*32*F_PAD   = 10752
//   sW0 : 32*F_PAD         =  2688  (pad column 83 = 0)
//   sW1 : 32*32            =  1024
//   sW2 : 32*32            =  1024
//   sB0/sB1/sB2 : 32 each  =    96
// total 15584 floats = 62336 bytes  (dynamic, needs MaxDynamicSharedMemorySize)
#define SMEM_FLOATS 15584
#define SMEM_BYTES  (SMEM_FLOATS * 4)

__device__ __forceinline__ unsigned long long pack2(float lo, float hi) {
    unsigned long long r;
    asm("mov.b64 %0, {%1, %2};" : "=l"(r) : "f"(lo), "f"(hi));
    return r;
}
__device__ __forceinline__ void unpack2(unsigned long long v, float& lo, float& hi) {
    asm("mov.b64 {%0, %1}, %2;" : "=f"(lo), "=f"(hi) : "l"(v));
}
// packed dual-fp32 FMA: d = a*b + d   (2 fp32 FMAs per instruction)
__device__ __forceinline__ void fma2(unsigned long long& d, unsigned long long a, unsigned long long b) {
    asm("fma.rn.f32x2 %0, %1, %2, %0;" : "+l"(d) : "l"(a), "l"(b));
}

__device__ __forceinline__ float gelu_exact(float v) {
    // exact gelu: v * Phi(v) = 0.5*v*(1+erf(v/sqrt(2)))
    return 0.5f * v * (1.0f + erff(v * 0.70710678118654752440f));
}

// one 32x32 layer: h_out[j] = gelu( b[j] + sum_k h_in[k]*W[j][k] )
__device__ __forceinline__ void layer32(const float* __restrict__ sW,
                                        const float* __restrict__ sB,
                                        const unsigned long long* __restrict__ hp,
                                        float* __restrict__ hout) {
#pragma unroll
    for (int j = 0; j < DD; j++) {
        const ulonglong2* wp = (const ulonglong2*)(sW + j * DD);
        unsigned long long acc = pack2(sB[j], 0.0f);
#pragma unroll
        for (int q = 0; q < 8; q++) {
            ulonglong2 w = wp[q];               // LDS.128, warp-uniform broadcast
            fma2(acc, hp[2 * q],     w.x);
            fma2(acc, hp[2 * q + 1], w.y);
        }
        float lo, hi; unpack2(acc, lo, hi);
        hout[j] = gelu_exact(lo + hi);
    }
}

__global__ void __launch_bounds__(THREADS)
material_encoder_kernel(const float* __restrict__ in,
                        const float* __restrict__ shiftp,
                        const float* __restrict__ W0, const float* __restrict__ b0,
                        const float* __restrict__ W1, const float* __restrict__ b1,
                        const float* __restrict__ W2, const float* __restrict__ b2,
                        float* __restrict__ out,
                        float* __restrict__ mask_out,
                        int n)
{
    extern __shared__ float sm[];
    float* sIn = sm;                                   // WARPS*32*F_PAD
    float* sW0 = sIn + WARPS * 32 * F_PAD;             // 32*F_PAD
    float* sW1 = sW0 + DD * F_PAD;
    float* sW2 = sW1 + DD * DD;
    float* sB0 = sW2 + DD * DD;
    float* sB1 = sB0 + DD;
    float* sB2 = sB1 + DD;

    const int tid = threadIdx.x;

    // ---- cooperative weight load (padded W0) ----
    for (int i = tid; i < DD * F_PAD; i += THREADS) {
        int j = i / F_PAD, k = i - j * F_PAD;
        sW0[i] = (k < F_IN) ? W0[j * F_IN + k] : 0.0f;
    }
    for (int i = tid; i < DD * DD; i += THREADS) { sW1[i] = W1[i]; sW2[i] = W2[i]; }
    if (tid < DD) { sB0[tid] = b0[tid]; sB1[tid] = b1[tid]; sB2[tid] = b2[tid]; }

    const float shift = __ldg(shiftp);

    const int warp = tid >> 5, lane = tid & 31;
    const long long rowBase = (long long)blockIdx.x * THREADS + warp * 32;
    const int rowsInWarp = (int)min((long long)32, (long long)n - rowBase);

    // ---- warp-cooperative staging: 32 rows x 83 floats, fully coalesced LDG ----
    float* wIn = sIn + warp * 32 * F_PAD;
    if (rowsInWarp == 32) {
        const float* gsrc = in + rowBase * F_IN;
#pragma unroll
        for (int i = 0; i < F_IN; i++) {
            int idx = i * 32 + lane;                   // 0..2655, contiguous per LDG
            float v = gsrc[idx];
            int r = idx / F_IN, c = idx - r * F_IN;
            wIn[r * F_PAD + c] = v;
        }
        wIn[lane * F_PAD + F_IN] = 0.0f;               // pad column
    } else if (rowsInWarp > 0) {
        for (int idx = lane; idx < rowsInWarp * F_IN; idx += 32) {
            int r = idx / F_IN, c = idx - r * F_IN;
            wIn[r * F_PAD + c] = in[(rowBase + r) * F_IN + c];
        }
        for (int r = lane; r < rowsInWarp; r += 32) wIn[r * F_PAD + F_IN] = 0.0f;
    }
    __syncthreads();

    const long long row = rowBase + lane;
    if (row >= n) return;

    // ---- load own row into packed registers, apply zero->shift + mask ----
    unsigned long long xp[F_PAD / 2];                  // 42 packed pairs
    bool any = false;
    {
        const float4* rp = (const float4*)(wIn + lane * F_PAD);  // conflict-free: stride 84 words
#pragma unroll
        for (int q = 0; q < F_PAD / 4; q++) {          // 21 x LDS.128
            float4 v = rp[q];
            any |= (v.x != 0.0f) | (v.y != 0.0f) | (v.z != 0.0f) | (v.w != 0.0f);
            float a0 = (v.x == 0.0f) ? shift : v.x;
            float a1 = (v.y == 0.0f) ? shift : v.y;
            float a2 = (v.z == 0.0f) ? shift : v.z;
            float a3 = (v.w == 0.0f) ? shift : v.w;
            xp[2 * q]     = pack2(a0, a1);
            xp[2 * q + 1] = pack2(a2, a3);
        }
        // note: pad element (col 83) is 0 -> becomes shift, but sW0 pad col is 0,
        // so its contribution is shift*0 = 0; it also never touches `any` (v==0 there
        // only if the real data at that slot was... it's the pad slot, always 0). correct.
    }

    // ---- layer 0: 83 -> 32 ----
    float h[DD];
#pragma unroll
    for (int j = 0; j < DD; j++) {
        const ulonglong2* wp = (const ulonglong2*)(sW0 + j * F_PAD);
        unsigned long long acc = pack2(sB0[j], 0.0f);
#pragma unroll
        for (int q = 0; q < F_PAD / 4; q++) {          // 21 x LDS.128 broadcast
            ulonglong2 w = wp[q];
            fma2(acc, xp[2 * q],     w.x);
            fma2(acc, xp[2 * q + 1], w.y);
        }
        float lo, hi; unpack2(acc, lo, hi);
        h[j] = gelu_exact(lo + hi);
    }

    // ---- layers 1 & 2: 32 -> 32 ----
    unsigned long long hp[DD / 2];
#pragma unroll
    for (int k = 0; k < DD / 2; k++) hp[k] = pack2(h[2 * k], h[2 * k + 1]);
    float h2[DD];
    layer32(sW1, sB1, hp, h2);
#pragma unroll
    for (int k = 0; k < DD / 2; k++) hp[k] = pack2(h2[2 * k], h2[2 * k + 1]);
    layer32(sW2, sB2, hp, h);

    // ---- L2 normalize + mask scatter ----
    float ss = 0.0f;
#pragma unroll
    for (int j = 0; j < DD; j++) ss += h[j] * h[j];
    float s = any ? rsqrtf(ss) : 0.0f;

    float4* op = (float4*)(out + row * DD);
#pragma unroll
    for (int q = 0; q < DD / 4; q++) {
        float4 o;
        o.x = h[4 * q]     * s;
        o.y = h[4 * q + 1] * s;
        o.z = h[4 * q + 2] * s;
        o.w = h[4 * q + 3] * s;
        op[q] = o;                                      // STG.128, warp-contiguous 4KB
    }
    if (mask_out) mask_out[row] = any ? 1.0f : 0.0f;
}

extern "C" void kernel_launch(void* const* d_in, const int* in_sizes, int n_in,
                              void* d_out, int out_size)
{
    const float* in  = (const float*)d_in[0];
    const float* sh  = (const float*)d_in[1];
    const float* W0  = (const float*)d_in[2];
    const float* b0  = (const float*)d_in[3];
    const float* W1  = (const float*)d_in[4];
    const float* b1  = (const float*)d_in[5];
    const float* W2  = (const float*)d_in[6];
    const float* b2  = (const float*)d_in[7];

    const int n = in_sizes[0] / F_IN;                  // 1048576
    float* out = (float*)d_out;
    // outputs are (x[n,32], mask[n]) flattened; write mask only if the buffer has room
    float* mask_out = (out_size >= n * (DD + 1)) ? (out + (long long)n * DD) : nullptr;

    static_assert(SMEM_BYTES == 62336, "smem layout");
    cudaFuncSetAttribute(material_encoder_kernel,
                         cudaFuncAttributeMaxDynamicSharedMemorySize, SMEM_BYTES);

    const int blocks = (n + THREADS - 1) / THREADS;
    material_encoder_kernel<<<blocks, THREADS, SMEM_BYTES>>>(
        in, sh, W0, b0, W1, b1, W2, b2, out, mask_out, n);
}

// round 2
// speedup vs baseline: 1.1162x; 1.1162x over previous
#include <cuda_runtime.h>
#include <math.h>

#define THREADS   256
#define WARPS     (THREADS/32)
#define F_IN      83
#define DD        32
#define W0PAD     84            // padded row for 16B-aligned weight pairs

// Shared layout (floats):
//   sIn : WARPS*32*F_IN = 21248   (linear staging, per-warp private)
//   sW0 : 32*84         =  2688   (pad col 83 = 0)
//   sW1 : 32*32         =  1024
//   sW2 : 32*32         =  1024
//   sB0/sB1/sB2         =    96
#define SIN_FL   (WARPS * 32 * F_IN)
#define SMEM_FL  (SIN_FL + DD * W0PAD + DD * DD + DD * DD + 3 * DD)
#define SMEM_BYTES (SMEM_FL * 4)

__device__ __forceinline__ unsigned long long pack2(float lo, float hi) {
    unsigned long long r;
    asm("mov.b64 %0, {%1, %2};" : "=l"(r) : "f"(lo), "f"(hi));
    return r;
}
__device__ __forceinline__ void unpack2(unsigned long long v, float& lo, float& hi) {
    asm("mov.b64 {%0, %1}, %2;" : "=f"(lo), "=f"(hi) : "l"(v));
}
// packed dual-fp32 FMA: d = a*b + d  (2 fp32 FMAs / instruction)
__device__ __forceinline__ void fma2(unsigned long long& d, unsigned long long a, unsigned long long b) {
    asm("fma.rn.f32x2 %0, %1, %2, %0;" : "+l"(d) : "l"(a), "l"(b));
}

__device__ __forceinline__ float gelu_exact(float v) {
    return 0.5f * v * (1.0f + erff(v * 0.70710678118654752440f));
}

__global__ void __launch_bounds__(THREADS, 2)
material_encoder_kernel(const float* __restrict__ in,
                        const float* __restrict__ shiftp,
                        const float* __restrict__ W0, const float* __restrict__ b0,
                        const float* __restrict__ W1, const float* __restrict__ b1,
                        const float* __restrict__ W2, const float* __restrict__ b2,
                        float* __restrict__ out,
                        float* __restrict__ mask_out,
                        int n)
{
    extern __shared__ float sm[];
    float* sIn = sm;                       // linear, per-warp 32*83 floats
    float* sW0 = sm + SIN_FL;
    float* sW1 = sW0 + DD * W0PAD;
    float* sW2 = sW1 + DD * DD;
    float* sB0 = sW2 + DD * DD;
    float* sB1 = sB0 + DD;
    float* sB2 = sB1 + DD;

    const int tid = threadIdx.x;

    // ---- cooperative weight load (W0 padded to 84, pad col = 0) ----
    for (int i = tid; i < DD * W0PAD; i += THREADS) {
        int j = i / W0PAD, k = i - j * W0PAD;
        sW0[i] = (k < F_IN) ? W0[j * F_IN + k] : 0.0f;
    }
    for (int i = tid; i < DD * DD; i += THREADS) { sW1[i] = W1[i]; sW2[i] = W2[i]; }
    if (tid < DD) { sB0[tid] = b0[tid]; sB1[tid] = b1[tid]; sB2[tid] = b2[tid]; }
    const float shift = __ldg(shiftp);
    __syncthreads();

    const int warp = tid >> 5, lane = tid & 31;
    const long long rowBase = (long long)blockIdx.x * THREADS + warp * 32;

    // ---- staging: copy warp's 32 contiguous rows (2656 floats) linearly ----
    // 664 float4 per warp, fully coalesced, no per-element index math.
    float* wbuf = sIn + warp * (32 * F_IN);
    if (rowBase + 32 <= (long long)n) {
        const float4* g4 = (const float4*)(in + rowBase * F_IN);   // 16B aligned: 32*83*4 % 16 == 0
        float4* s4 = (float4*)wbuf;
#pragma unroll
        for (int i = 0; i < 21; i++) {
            int idx = i * 32 + lane;
            if (idx < (32 * F_IN) / 4) s4[idx] = g4[idx];
        }
    } else if (rowBase < (long long)n) {
        int valid = (int)((long long)n - rowBase);
        for (int idx = lane; idx < valid * F_IN; idx += 32)
            wbuf[idx] = in[rowBase * F_IN + idx];
    }
    __syncwarp();

    const long long row = rowBase + lane;
    if (row >= (long long)n) return;

    // own row: scalar LDS, conflict-free (lane stride 83 words, gcd(83,32)=1)
    const float* xr = wbuf + lane * F_IN;

    // ---- layer 0: 83 -> 32, accumulator-blocked ----
    unsigned long long acc[DD];
#pragma unroll
    for (int j = 0; j < DD; j++) acc[j] = 0ULL;

    unsigned int anyb = 0;                 // OR of |bits|: -0.0-safe "any nonzero"
    const unsigned int ABSM = 0x7fffffffu;

    for (int c = 0; c < 10; c++) {         // 10 chunks of 8 cols (0..79)
        const int c0 = c * 8;
        unsigned long long xp[4];
#pragma unroll
        for (int t = 0; t < 4; t++) {
            float v0 = xr[c0 + 2 * t], v1 = xr[c0 + 2 * t + 1];
            anyb |= (__float_as_uint(v0) & ABSM);
            anyb |= (__float_as_uint(v1) & ABSM);
            float a0 = (v0 == 0.0f) ? shift : v0;
            float a1 = (v1 == 0.0f) ? shift : v1;
            xp[t] = pack2(a0, a1);
        }
        const float* wrow = sW0 + c0;
#pragma unroll
        for (int j = 0; j < DD; j++) {
            ulonglong2 wa = *(const ulonglong2*)(wrow + j * W0PAD);      // LDS.128 bcast
            ulonglong2 wb = *(const ulonglong2*)(wrow + j * W0PAD + 4);
            fma2(acc[j], xp[0], wa.x);
            fma2(acc[j], xp[1], wa.y);
            fma2(acc[j], xp[2], wb.x);
            fma2(acc[j], xp[3], wb.y);
        }
    }
    {   // tail: cols 80..82 (+ zero pad col 83)
        float v0 = xr[80], v1 = xr[81], v2 = xr[82];
        anyb |= (__float_as_uint(v0) & ABSM);
        anyb |= (__float_as_uint(v1) & ABSM);
        anyb |= (__float_as_uint(v2) & ABSM);
        float a0 = (v0 == 0.0f) ? shift : v0;
        float a1 = (v1 == 0.0f) ? shift : v1;
        float a2 = (v2 == 0.0f) ? shift : v2;
        unsigned long long xp0 = pack2(a0, a1);
        unsigned long long xp1 = pack2(a2, 0.0f);     // pad weight col is 0 anyway
#pragma unroll
        for (int j = 0; j < DD; j++) {
            ulonglong2 w = *(const ulonglong2*)(sW0 + j * W0PAD + 80);
            fma2(acc[j], xp0, w.x);
            fma2(acc[j], xp1, w.y);
        }
    }

    float h[DD];
#pragma unroll
    for (int j = 0; j < DD; j++) {
        float lo, hi; unpack2(acc[j], lo, hi);
        h[j] = gelu_exact(lo + hi + sB0[j]);
    }

    // ---- layer 1: 32 -> 32 ----
    unsigned long long hp[DD / 2];
#pragma unroll
    for (int k = 0; k < DD / 2; k++) hp[k] = pack2(h[2 * k], h[2 * k + 1]);
    float h2[DD];
#pragma unroll
    for (int j = 0; j < DD; j++) {
        const ulonglong2* wp = (const ulonglong2*)(sW1 + j * DD);
        unsigned long long a = 0ULL;
#pragma unroll
        for (int q = 0; q < 8; q++) {
            ulonglong2 w = wp[q];
            fma2(a, hp[2 * q],     w.x);
            fma2(a, hp[2 * q + 1], w.y);
        }
        float lo, hi; unpack2(a, lo, hi);
        h2[j] = gelu_exact(lo + hi + sB1[j]);
    }

    // ---- layer 2: 32 -> 32 ----
#pragma unroll
    for (int k = 0; k < DD / 2; k++) hp[k] = pack2(h2[2 * k], h2[2 * k + 1]);
#pragma unroll
    for (int j = 0; j < DD; j++) {
        const ulonglong2* wp = (const ulonglong2*)(sW2 + j * DD);
        unsigned long long a = 0ULL;
#pragma unroll
        for (int q = 0; q < 8; q++) {
            ulonglong2 w = wp[q];
            fma2(a, hp[2 * q],     w.x);
            fma2(a, hp[2 * q + 1], w.y);
        }
        float lo, hi; unpack2(a, lo, hi);
        h[j] = gelu_exact(lo + hi + sB2[j]);
    }

    // ---- L2 normalize + mask scatter ----
    float ss = 0.0f;
#pragma unroll
    for (int j = 0; j < DD; j++) ss += h[j] * h[j];
    const bool any = (anyb != 0u);
    const float s = any ? rsqrtf(ss) : 0.0f;

    float4* op = (float4*)(out + row * DD);
#pragma unroll
    for (int q = 0; q < DD / 4; q++) {
        float4 o;
        o.x = h[4 * q]     * s;
        o.y = h[4 * q + 1] * s;
        o.z = h[4 * q + 2] * s;
        o.w = h[4 * q + 3] * s;
        op[q] = o;
    }
    if (mask_out) mask_out[row] = any ? 1.0f : 0.0f;
}

extern "C" void kernel_launch(void* const* d_in, const int* in_sizes, int n_in,
                              void* d_out, int out_size)
{
    const float* in  = (const float*)d_in[0];
    const float* sh  = (const float*)d_in[1];
    const float* W0  = (const float*)d_in[2];
    const float* b0  = (const float*)d_in[3];
    const float* W1  = (const float*)d_in[4];
    const float* b1  = (const float*)d_in[5];
    const float* W2  = (const float*)d_in[6];
    const float* b2  = (const float*)d_in[7];

    const int n = in_sizes[0] / F_IN;
    float* out = (float*)d_out;
    float* mask_out = (out_size >= n * (DD + 1)) ? (out + (long long)n * DD) : nullptr;

    cudaFuncSetAttribute(material_encoder_kernel,
                         cudaFuncAttributeMaxDynamicSharedMemorySize, SMEM_BYTES);

    const int blocks = (n + THREADS - 1) / THREADS;
    material_encoder_kernel<<<blocks, THREADS, SMEM_BYTES>>>(
        in, sh, W0, b0, W1, b1, W2, b2, out, mask_out, n);
}